// round 15
// baseline (speedup 1.0000x reference)
#include <cuda_runtime.h>
#include <cuda_bf16.h>
#include <cstdint>

#define N_NODES 50000
#define N_REL   16
#define N_BASIS 8
#define D_IN    64
#define D_HID   64
#define N_CLASS 16
#define N_EDGES 800000

#define ES      802176              // 6267 * 128 (16 bins padded to 128)
#define NBLK_E  6267

// ---------------- device scratch ----------------
// B fragments for mma.sync m16n8k16 row.col, PTX-lane layout:
// idx = ((((rel*2 + hl)*4 + ks)*NT + nt)*32 + lane)*2 + j
__device__ __align__(16) uint32_t g_W1f[N_REL * 2 * 4 * 8 * 32 * 2];   // 128 KB
__device__ __align__(16) uint32_t g_W2f[N_REL * 2 * 4 * 2 * 32 * 2];   // 32 KB
__device__ __align__(16) __nv_bfloat16 g_Xh[N_NODES * 64];
__device__ __align__(16) __nv_bfloat16 g_Xl[N_NODES * 64];
__device__ __align__(16) __nv_bfloat16 g_Hh[N_NODES * 64];
__device__ __align__(16) __nv_bfloat16 g_Hl[N_NODES * 64];
__device__ __align__(16) float g_h [N_NODES * D_HID];
__device__ __align__(16) int   g_cnt[N_REL * N_NODES];
__device__ int   g_hist[N_REL];
__device__ int   g_sortrel[N_REL];
__device__ __align__(16) int   g_s[ES];
__device__ __align__(16) int   g_d[ES];
__device__ __align__(16) float g_v[ES];

// ---------------- helpers ----------------
__device__ __forceinline__ uint32_t sw128(uint32_t o) { return o ^ ((o >> 3) & 0x70); }
__device__ __forceinline__ uint32_t smem_u32(const void* p) {
    uint32_t a;
    asm("{ .reg .u64 t; cvta.to.shared.u64 t, %1; cvt.u32.u64 %0, t; }" : "=r"(a) : "l"(p));
    return a;
}
__device__ __forceinline__ void cp_async16(uint32_t dst, const void* src) {
    asm volatile("cp.async.cg.shared.global [%0], [%1], 16;" :: "r"(dst), "l"(src) : "memory");
}
__device__ __forceinline__ void cp_commit() {
    asm volatile("cp.async.commit_group;" ::: "memory");
}
template<int N>
__device__ __forceinline__ void cp_wait() {
    asm volatile("cp.async.wait_group %0;" :: "n"(N) : "memory");
}
__device__ __forceinline__ void red_v4(float* p, float a, float b, float c, float d) {
    asm volatile("red.global.add.v4.f32 [%0], {%1, %2, %3, %4};"
                 :: "l"(p), "f"(a), "f"(b), "f"(c), "f"(d) : "memory");
}
__device__ __forceinline__ void bf16_split(float v, __nv_bfloat16& hi, __nv_bfloat16& lo) {
    hi = __float2bfloat16(v);
    lo = __float2bfloat16(v - __bfloat162float(hi));
}
__device__ __forceinline__ void ldm_x4(uint32_t& a0, uint32_t& a1, uint32_t& a2, uint32_t& a3,
                                       uint32_t addr) {
    asm volatile("ldmatrix.sync.aligned.m8n8.x4.shared.b16 {%0,%1,%2,%3}, [%4];"
                 : "=r"(a0), "=r"(a1), "=r"(a2), "=r"(a3) : "r"(addr));
}
__device__ __forceinline__ void mma_bf16(float& c0, float& c1, float& c2, float& c3,
                                         uint32_t a0, uint32_t a1, uint32_t a2, uint32_t a3,
                                         uint32_t b0, uint32_t b1) {
    asm volatile("mma.sync.aligned.m16n8k16.row.col.f32.bf16.bf16.f32 "
                 "{%0,%1,%2,%3}, {%4,%5,%6,%7}, {%8,%9}, {%0,%1,%2,%3};"
                 : "+f"(c0), "+f"(c1), "+f"(c2), "+f"(c3)
                 : "r"(a0), "r"(a1), "r"(a2), "r"(a3), "r"(b0), "r"(b1));
}

// ---------------- init: W frags (split, lane layout), X split, zero state ----------------
__global__ void k_init(const float* __restrict__ bases1, const float* __restrict__ coeffs1,
                       const float* __restrict__ bases2, const float* __restrict__ coeffs2,
                       const float* __restrict__ x)
{
    int nthreads = gridDim.x * blockDim.x;
    int gt = blockIdx.x * blockDim.x + threadIdx.x;

    // layer-1 B fragments: NT=8
    for (int idx = gt; idx < N_REL * 2 * 4 * 8 * 32 * 2; idx += nthreads) {
        int j    = idx & 1;
        int lane = (idx >> 1) & 31;
        int nt   = (idx >> 6) & 7;
        int ks   = (idx >> 9) & 3;
        int hl   = (idx >> 11) & 1;
        int rel  = idx >> 12;
        int n  = nt * 8 + (lane >> 2);
        int k0 = ks * 16 + (lane & 3) * 2 + j * 8;
        float w0 = 0.f, w1 = 0.f;
        #pragma unroll
        for (int b = 0; b < N_BASIS; b++) {
            float c = coeffs1[rel * N_BASIS + b];
            w0 += c * bases1[b * 4096 + k0 * 64 + n];
            w1 += c * bases1[b * 4096 + (k0 + 1) * 64 + n];
        }
        __nv_bfloat16 h0, l0, h1, l1;
        bf16_split(w0, h0, l0); bf16_split(w1, h1, l1);
        uint16_t u0 = hl ? __bfloat16_as_ushort(l0) : __bfloat16_as_ushort(h0);
        uint16_t u1 = hl ? __bfloat16_as_ushort(l1) : __bfloat16_as_ushort(h1);
        g_W1f[idx] = (uint32_t)u0 | ((uint32_t)u1 << 16);
    }
    // layer-2 B fragments: NT=2
    for (int idx = gt; idx < N_REL * 2 * 4 * 2 * 32 * 2; idx += nthreads) {
        int j    = idx & 1;
        int lane = (idx >> 1) & 31;
        int nt   = (idx >> 6) & 1;
        int ks   = (idx >> 7) & 3;
        int hl   = (idx >> 9) & 1;
        int rel  = idx >> 10;
        int n  = nt * 8 + (lane >> 2);
        int k0 = ks * 16 + (lane & 3) * 2 + j * 8;
        float w0 = 0.f, w1 = 0.f;
        #pragma unroll
        for (int b = 0; b < N_BASIS; b++) {
            float c = coeffs2[rel * N_BASIS + b];
            w0 += c * bases2[b * 1024 + k0 * 16 + n];
            w1 += c * bases2[b * 1024 + (k0 + 1) * 16 + n];
        }
        __nv_bfloat16 h0, l0, h1, l1;
        bf16_split(w0, h0, l0); bf16_split(w1, h1, l1);
        uint16_t u0 = hl ? __bfloat16_as_ushort(l0) : __bfloat16_as_ushort(h0);
        uint16_t u1 = hl ? __bfloat16_as_ushort(l1) : __bfloat16_as_ushort(h1);
        g_W2f[idx] = (uint32_t)u0 | ((uint32_t)u1 << 16);
    }
    for (int j = gt; j < N_NODES * 64; j += nthreads) {
        __nv_bfloat16 hi, lo; bf16_split(x[j], hi, lo);
        g_Xh[j] = hi; g_Xl[j] = lo;
    }
    for (int i = gt; i < N_REL * N_NODES; i += nthreads) g_cnt[i] = 0;
    for (int i = gt; i < ES; i += nthreads) { g_s[i] = 0; g_d[i] = 0; g_v[i] = 0.f; }
    if (gt < N_REL) { g_hist[gt] = 0; g_sortrel[gt] = 0; }
}

// ---------------- count + histogram ----------------
__global__ void k_counthist(const int* __restrict__ ei, const int* __restrict__ et)
{
    __shared__ int lh[N_REL];
    if (threadIdx.x < N_REL) lh[threadIdx.x] = 0;
    __syncthreads();
    int e = blockIdx.x * blockDim.x + threadIdx.x;
    if (e < N_EDGES) {
        int dst = __ldg(&ei[N_EDGES + e]);
        int t   = __ldg(&et[e]);
        atomicAdd(&g_cnt[t * N_NODES + dst], 1);
        atomicAdd(&lh[t], 1);
    }
    __syncthreads();
    if (threadIdx.x < N_REL && lh[threadIdx.x] > 0)
        atomicAdd(&g_hist[threadIdx.x], lh[threadIdx.x]);
}

// ---------------- counting-sort permute + inv ----------------
__global__ void k_permute(const int* __restrict__ ei, const int* __restrict__ et)
{
    __shared__ int spad[N_REL];
    if (threadIdx.x == 0) {
        int off = 0;
        #pragma unroll
        for (int r = 0; r < N_REL; r++) { spad[r] = off; off += ((g_hist[r] + 127) & ~127); }
    }
    __syncthreads();

    int e = blockIdx.x * blockDim.x + threadIdx.x;
    if (e >= N_EDGES) return;
    int src = __ldg(&ei[e]);
    int dst = __ldg(&ei[N_EDGES + e]);
    int t   = __ldg(&et[e]);
    int lane = threadIdx.x & 31;

    unsigned mask = __match_any_sync(__activemask(), t);
    int leader = __ffs(mask) - 1;
    int rank   = __popc(mask & ((1u << lane) - 1));
    int base = 0;
    if (lane == leader) base = atomicAdd(&g_sortrel[t], __popc(mask));
    base = __shfl_sync(__activemask(), base, leader);
    int pos = spad[t] + base + rank;

    int cnt = g_cnt[t * N_NODES + dst];
    g_s[pos] = src;
    g_d[pos] = dst;
    g_v[pos] = 1.0f / (float)(cnt > 0 ? cnt : 1);
}

// ---------------- split relu(h) into bf16 hi/lo ----------------
__global__ void k_splith()
{
    int j = blockIdx.x * blockDim.x + threadIdx.x;
    if (j >= N_NODES * 64) return;
    float v = fmaxf(g_h[j], 0.f);
    __nv_bfloat16 hi, lo; bf16_split(v, hi, lo);
    g_Hh[j] = hi; g_Hl[j] = lo;
}

// ---------------- HMMA fused edge GEMM: dest[dst] += inv * (X[src] @ W_rel) ----------------
// 128 edges/block, 8 warps; each warp owns ONE m16 tile (16 edges). cp.async in
// 2 groups: {Ah, B} then {Al}; passes Ah*Wh+Ah*Wl after group0, Al*Wh after group1.
template<int NOUT, int MAXB>
__global__ __launch_bounds__(256, MAXB) void k_hmma(const __nv_bfloat16* __restrict__ Xh,
                                                    const __nv_bfloat16* __restrict__ Xl,
                                                    const uint32_t* __restrict__ Wf,
                                                    float* __restrict__ dest)
{
    constexpr int NT = NOUT / 8;                    // n-tiles (8 or 2)
    constexpr int WFREL = 2 * 4 * NT * 32 * 2;      // u32 per relation

    extern __shared__ __align__(128) char dsm[];
    // layout: Ah @0 (16KB), Al @16384 (16KB), B @32768 (WFREL*4)
    uint32_t* bfs = (uint32_t*)(dsm + 32768);

    __shared__ int   ssrc[128];
    __shared__ int   ds[128];
    __shared__ float vs[128];
    __shared__ int   spad[N_REL];

    const int tid = threadIdx.x, lane = tid & 31, wid = tid >> 5;
    const int b0 = blockIdx.x * 128;

    if (tid == 0) {
        int off = 0;
        #pragma unroll
        for (int r = 0; r < N_REL; r++) { spad[r] = off; off += ((g_hist[r] + 127) & ~127); }
    }
    if (tid < 128) {
        ssrc[tid] = g_s[b0 + tid];
        ds[tid]   = g_d[b0 + tid];
        vs[tid]   = g_v[b0 + tid];
    }
    __syncthreads();

    int rel = 0;
    #pragma unroll
    for (int i = 1; i < N_REL; i++)
        if (b0 >= spad[i]) rel = i;

    const uint32_t a_base = smem_u32(dsm);
    const uint32_t b_base = a_base + 32768;

    // group 0: Ah rows (warp stages its own 16 rows) + B fragments (block-strided)
    #pragma unroll
    for (int i = 0; i < 4; i++) {
        int row = wid * 16 + i * 4 + (lane >> 3);
        int c   = (lane & 7) * 16;
        int src = ssrc[row];
        cp_async16(a_base + sw128((uint32_t)(row * 128 + c)),
                   (const char*)Xh + (size_t)src * 128 + c);
    }
    {
        const uint32_t* wsrc = Wf + (size_t)rel * WFREL;
        for (int i = tid * 4; i < WFREL; i += 256 * 4)
            cp_async16(b_base + i * 4, wsrc + i);
    }
    cp_commit();
    // group 1: Al rows (per-warp)
    #pragma unroll
    for (int i = 0; i < 4; i++) {
        int row = wid * 16 + i * 4 + (lane >> 3);
        int c   = (lane & 7) * 16;
        int src = ssrc[row];
        cp_async16(a_base + 16384 + sw128((uint32_t)(row * 128 + c)),
                   (const char*)Xl + (size_t)src * 128 + c);
    }
    cp_commit();

    cp_wait<1>();           // Ah + B ready
    __syncthreads();

    float acc[NT][4];
    #pragma unroll
    for (int nt = 0; nt < NT; nt++)
        #pragma unroll
        for (int j = 0; j < 4; j++) acc[nt][j] = 0.f;

    const int lrow = lane & 15;
    const int lkh  = lane >> 4;

    // passes 1+2: Ah*Wh and Ah*Wl
    #pragma unroll
    for (int ks = 0; ks < 4; ks++) {
        int row = wid * 16 + lrow;
        int c   = ks * 2 + lkh;
        uint32_t off = (uint32_t)(row * 128) + (uint32_t)((c ^ (row & 7)) << 4);
        uint32_t ah0, ah1, ah2, ah3;
        ldm_x4(ah0, ah1, ah2, ah3, a_base + off);
        #pragma unroll
        for (int nt = 0; nt < NT; nt++) {
            const uint32_t* ph = bfs + (((0 * 4 + ks) * NT + nt) * 32 + lane) * 2;
            const uint32_t* pl = bfs + (((1 * 4 + ks) * NT + nt) * 32 + lane) * 2;
            mma_bf16(acc[nt][0], acc[nt][1], acc[nt][2], acc[nt][3],
                     ah0, ah1, ah2, ah3, ph[0], ph[1]);
            mma_bf16(acc[nt][0], acc[nt][1], acc[nt][2], acc[nt][3],
                     ah0, ah1, ah2, ah3, pl[0], pl[1]);
        }
    }

    cp_wait<0>();           // Al ready (staged by this warp)
    __syncwarp();

    // pass 3: Al*Wh
    #pragma unroll
    for (int ks = 0; ks < 4; ks++) {
        int row = wid * 16 + lrow;
        int c   = ks * 2 + lkh;
        uint32_t off = (uint32_t)(row * 128) + (uint32_t)((c ^ (row & 7)) << 4);
        uint32_t al0, al1, al2, al3;
        ldm_x4(al0, al1, al2, al3, a_base + 16384 + off);
        #pragma unroll
        for (int nt = 0; nt < NT; nt++) {
            const uint32_t* ph = bfs + (((0 * 4 + ks) * NT + nt) * 32 + lane) * 2;
            mma_bf16(acc[nt][0], acc[nt][1], acc[nt][2], acc[nt][3],
                     al0, al1, al2, al3, ph[0], ph[1]);
        }
    }

    // epilogue: pair-exchange via shfl.xor(1) -> one red.v4 per nt
    const int q    = lane & 3;
    const int crow = lane >> 2;
    const bool odd = (lane & 1);
    {
        int rowE = wid * 16 + crow;
        int row  = odd ? rowE + 8 : rowE;
        float inv = vs[row];
        float* rp = dest + (size_t)ds[row] * NOUT;
        int colbase = odd ? 2 * (q - 1) : 2 * q;
        #pragma unroll
        for (int nt = 0; nt < NT; nt++) {
            float s0 = odd ? acc[nt][0] : acc[nt][2];
            float s1 = odd ? acc[nt][1] : acc[nt][3];
            unsigned long long pk;
            asm("mov.b64 %0, {%1, %2};" : "=l"(pk) : "f"(s0), "f"(s1));
            unsigned long long rk = __shfl_xor_sync(0xFFFFFFFFu, pk, 1);
            float r0, r1;
            asm("mov.b64 {%0, %1}, %2;" : "=f"(r0), "=f"(r1) : "l"(rk));
            float v0, v1, v2, v3;
            if (odd) { v0 = r0; v1 = r1; v2 = acc[nt][2]; v3 = acc[nt][3]; }
            else     { v0 = acc[nt][0]; v1 = acc[nt][1]; v2 = r0; v3 = r1; }
            red_v4(rp + nt * 8 + colbase, v0 * inv, v1 * inv, v2 * inv, v3 * inv);
        }
    }
}

// ---------------- dense self-term GEMM (exact f32): OUT (+)= act(X) @ W ----------------
template<int NOUT, bool RELU, bool ATOMIC>
__global__ __launch_bounds__(128) void k_dense(const float* __restrict__ X,
                                               const float* __restrict__ W,
                                               float* __restrict__ OUT)
{
    constexpr int TO  = NOUT / 4;
    constexpr int NW2 = TO / 2;

    __shared__ float xs[64][128];
    __shared__ float ws[64 * NOUT];

    const int tid  = threadIdx.x;
    const int lane = tid & 31;
    const int og   = tid >> 5;
    const int b0   = blockIdx.x * 128;

    #pragma unroll
    for (int i = 0; i < 16; i++) {
        int row = og * 32 + i * 2 + (lane >> 4);
        int g   = lane & 15;
        int node = b0 + row;
        float4 v = make_float4(0.f, 0.f, 0.f, 0.f);
        if (node < N_NODES) v = __ldg((const float4*)(X + (size_t)node * 64 + g * 4));
        if (RELU) {
            v.x = fmaxf(v.x, 0.f); v.y = fmaxf(v.y, 0.f);
            v.z = fmaxf(v.z, 0.f); v.w = fmaxf(v.w, 0.f);
        }
        int mp = row ^ ((g & 7) << 2);
        xs[4 * g + 0][mp] = v.x;
        xs[4 * g + 1][mp] = v.y;
        xs[4 * g + 2][mp] = v.z;
        xs[4 * g + 3][mp] = v.w;
    }
    for (int i = tid * 4; i < 64 * NOUT; i += 128 * 4)
        *(float4*)(ws + i) = *(const float4*)(W + i);
    __syncthreads();

    const int o0 = og * TO;
    const int m0 = lane * 4;

    unsigned long long acc[4][NW2];
    #pragma unroll
    for (int i = 0; i < 4; i++)
        #pragma unroll
        for (int j = 0; j < NW2; j++) acc[i][j] = 0ull;

    #pragma unroll 8
    for (int k = 0; k < 64; k++) {
        float4 xv = *(const float4*)&xs[k][m0 ^ (k & 28)];
        unsigned long long x2[4];
        asm("mov.b64 %0, {%1, %1};" : "=l"(x2[0]) : "f"(xv.x));
        asm("mov.b64 %0, {%1, %1};" : "=l"(x2[1]) : "f"(xv.y));
        asm("mov.b64 %0, {%1, %1};" : "=l"(x2[2]) : "f"(xv.z));
        asm("mov.b64 %0, {%1, %1};" : "=l"(x2[3]) : "f"(xv.w));
        unsigned long long w2[NW2];
        #pragma unroll
        for (int q = 0; q < TO / 4; q++) {
            float4 wa = *(const float4*)(ws + k * NOUT + o0 + q * 4);
            asm("mov.b64 %0, {%1, %2};" : "=l"(w2[q * 2 + 0]) : "f"(wa.x), "f"(wa.y));
            asm("mov.b64 %0, {%1, %2};" : "=l"(w2[q * 2 + 1]) : "f"(wa.z), "f"(wa.w));
        }
        #pragma unroll
        for (int j = 0; j < NW2; j++)
            #pragma unroll
            for (int i = 0; i < 4; i++)
                asm("fma.rn.f32x2 %0, %1, %2, %0;" : "+l"(acc[i][j]) : "l"(x2[i]), "l"(w2[j]));
    }

    #pragma unroll
    for (int i = 0; i < 4; i++) {
        int node = b0 + m0 + i;
        if (node < N_NODES) {
            float* op = OUT + (size_t)node * NOUT + o0;
            #pragma unroll
            for (int j = 0; j < NW2; j += 2) {
                float2 a = *(float2*)&acc[i][j];
                float2 b = *(float2*)&acc[i][j + 1];
                if (ATOMIC) red_v4(op + 2 * j, a.x, a.y, b.x, b.y);
                else *(float4*)(op + 2 * j) = make_float4(a.x, a.y, b.x, b.y);
            }
        }
    }
}

// ---------------- launch ----------------
extern "C" void kernel_launch(void* const* d_in, const int* in_sizes, int n_in,
                              void* d_out, int out_size)
{
    const float* x       = (const float*)d_in[0];
    const float* bases1  = (const float*)d_in[1];
    const float* coeffs1 = (const float*)d_in[2];
    const float* self1   = (const float*)d_in[3];
    const float* bases2  = (const float*)d_in[4];
    const float* coeffs2 = (const float*)d_in[5];
    const float* self2   = (const float*)d_in[6];
    const int* ei        = (const int*)d_in[7];
    const int* et        = (const int*)d_in[8];
    float* out = (float*)d_out;

    const int NODE_TILES = (N_NODES + 127) / 128;   // 391
    const int DSM1 = 32768 + 2 * 4 * 8 * 32 * 2 * 4;   // 49152
    const int DSM2 = 32768 + 2 * 4 * 2 * 32 * 2 * 4;   // 36864

    float* hp;  cudaGetSymbolAddress((void**)&hp,  g_h);
    uint32_t *w1f, *w2f;
    cudaGetSymbolAddress((void**)&w1f, g_W1f);
    cudaGetSymbolAddress((void**)&w2f, g_W2f);
    __nv_bfloat16 *xh, *xl, *hh, *hl;
    cudaGetSymbolAddress((void**)&xh, g_Xh);
    cudaGetSymbolAddress((void**)&xl, g_Xl);
    cudaGetSymbolAddress((void**)&hh, g_Hh);
    cudaGetSymbolAddress((void**)&hl, g_Hl);

    cudaFuncSetAttribute((const void*)k_hmma<D_HID, 3>,
                         cudaFuncAttributeMaxDynamicSharedMemorySize, DSM1);
    cudaFuncSetAttribute((const void*)k_hmma<N_CLASS, 4>,
                         cudaFuncAttributeMaxDynamicSharedMemorySize, DSM2);

    // #1 W fragments (split, mma lane layout) + X split + zero state
    k_init<<<1024, 256>>>(bases1, coeffs1, bases2, coeffs2, x);
    // #2 counts + histogram
    k_counthist<<<(N_EDGES + 255) / 256, 256>>>(ei, et);
    // #3 counting-sort by relation
    k_permute<<<(N_EDGES + 255) / 256, 256>>>(ei, et);
    // #4 (profiled): h = x @ self1 (plain store, covers h) -- runs before edge atomics
    k_dense<D_HID, false, false><<<NODE_TILES, 128>>>(x, self1, hp);
    // #5 layer-1 fused HMMA edge GEMM -> atomic into h
    k_hmma<D_HID, 3><<<NBLK_E, 256, DSM1>>>(xh, xl, w1f, hp);
    // #6 relu + bf16-split h
    k_splith<<<(N_NODES * 64 + 255) / 256, 256>>>();
    // #7 out = relu(h) @ self2 (plain store covers out)
    k_dense<N_CLASS, true, false><<<NODE_TILES, 128>>>(hp, self2, out);
    // #8 layer-2 fused HMMA edge GEMM -> atomic into out
    k_hmma<N_CLASS, 4><<<NBLK_E, 256, DSM2>>>(hh, hl, w2f, out);
}

// round 16
// speedup vs baseline: 1.0925x; 1.0925x over previous
#include <cuda_runtime.h>
#include <cuda_bf16.h>
#include <cstdint>

#define N_NODES 50000
#define N_REL   16
#define N_BASIS 8
#define D_IN    64
#define D_HID   64
#define N_CLASS 16
#define N_EDGES 800000

#define ES      802176              // 6267 * 128 (16 bins padded to 128)
#define NBLK_E  6267

// ---------------- device scratch ----------------
// B fragments for mma.sync m16n8k16 row.col, PTX-lane layout:
// idx = ((((rel*2 + hl)*4 + ks)*NT + nt)*32 + lane)*2 + j
__device__ __align__(16) uint32_t g_W1f[N_REL * 2 * 4 * 8 * 32 * 2];   // 128 KB
__device__ __align__(16) uint32_t g_W2f[N_REL * 2 * 4 * 2 * 32 * 2];   // 32 KB
__device__ __align__(16) __nv_bfloat16 g_Xh[N_NODES * 64];
__device__ __align__(16) __nv_bfloat16 g_Xl[N_NODES * 64];
__device__ __align__(16) __nv_bfloat16 g_Hh[N_NODES * 64];
__device__ __align__(16) __nv_bfloat16 g_Hl[N_NODES * 64];
__device__ __align__(16) float g_h [N_NODES * D_HID];
__device__ __align__(16) int   g_cnt[N_REL * N_NODES];
__device__ int   g_hist[N_REL];
__device__ int   g_sortrel[N_REL];
__device__ __align__(16) int   g_s[ES];
__device__ __align__(16) int   g_d[ES];
__device__ __align__(16) float g_v[ES];

// ---------------- helpers ----------------
__device__ __forceinline__ uint32_t sw128(uint32_t o) { return o ^ ((o >> 3) & 0x70); }
__device__ __forceinline__ uint32_t smem_u32(const void* p) {
    uint32_t a;
    asm("{ .reg .u64 t; cvta.to.shared.u64 t, %1; cvt.u32.u64 %0, t; }" : "=r"(a) : "l"(p));
    return a;
}
__device__ __forceinline__ void cp_async16(uint32_t dst, const void* src) {
    asm volatile("cp.async.cg.shared.global [%0], [%1], 16;" :: "r"(dst), "l"(src) : "memory");
}
__device__ __forceinline__ void cp_commit() {
    asm volatile("cp.async.commit_group;" ::: "memory");
}
template<int N>
__device__ __forceinline__ void cp_wait() {
    asm volatile("cp.async.wait_group %0;" :: "n"(N) : "memory");
}
__device__ __forceinline__ void red_v4(float* p, float a, float b, float c, float d) {
    asm volatile("red.global.add.v4.f32 [%0], {%1, %2, %3, %4};"
                 :: "l"(p), "f"(a), "f"(b), "f"(c), "f"(d) : "memory");
}
__device__ __forceinline__ void bf16_split(float v, __nv_bfloat16& hi, __nv_bfloat16& lo) {
    hi = __float2bfloat16(v);
    lo = __float2bfloat16(v - __bfloat162float(hi));
}
__device__ __forceinline__ void ldm_x4(uint32_t& a0, uint32_t& a1, uint32_t& a2, uint32_t& a3,
                                       uint32_t addr) {
    asm volatile("ldmatrix.sync.aligned.m8n8.x4.shared.b16 {%0,%1,%2,%3}, [%4];"
                 : "=r"(a0), "=r"(a1), "=r"(a2), "=r"(a3) : "r"(addr));
}
__device__ __forceinline__ void mma_bf16(float& c0, float& c1, float& c2, float& c3,
                                         uint32_t a0, uint32_t a1, uint32_t a2, uint32_t a3,
                                         uint32_t b0, uint32_t b1) {
    asm volatile("mma.sync.aligned.m16n8k16.row.col.f32.bf16.bf16.f32 "
                 "{%0,%1,%2,%3}, {%4,%5,%6,%7}, {%8,%9}, {%0,%1,%2,%3};"
                 : "+f"(c0), "+f"(c1), "+f"(c2), "+f"(c3)
                 : "r"(a0), "r"(a1), "r"(a2), "r"(a3), "r"(b0), "r"(b1));
}

// ---------------- init: W frags (split, lane layout), X split, zero state ----------------
__global__ void k_init(const float* __restrict__ bases1, const float* __restrict__ coeffs1,
                       const float* __restrict__ bases2, const float* __restrict__ coeffs2,
                       const float* __restrict__ x)
{
    int nthreads = gridDim.x * blockDim.x;
    int gt = blockIdx.x * blockDim.x + threadIdx.x;

    // layer-1 B fragments: NT=8
    for (int idx = gt; idx < N_REL * 2 * 4 * 8 * 32 * 2; idx += nthreads) {
        int j    = idx & 1;
        int lane = (idx >> 1) & 31;
        int nt   = (idx >> 6) & 7;
        int ks   = (idx >> 9) & 3;
        int hl   = (idx >> 11) & 1;
        int rel  = idx >> 12;
        int n  = nt * 8 + (lane >> 2);
        int k0 = ks * 16 + (lane & 3) * 2 + j * 8;
        float w0 = 0.f, w1 = 0.f;
        #pragma unroll
        for (int b = 0; b < N_BASIS; b++) {
            float c = coeffs1[rel * N_BASIS + b];
            w0 += c * bases1[b * 4096 + k0 * 64 + n];
            w1 += c * bases1[b * 4096 + (k0 + 1) * 64 + n];
        }
        __nv_bfloat16 h0, l0, h1, l1;
        bf16_split(w0, h0, l0); bf16_split(w1, h1, l1);
        uint16_t u0 = hl ? __bfloat16_as_ushort(l0) : __bfloat16_as_ushort(h0);
        uint16_t u1 = hl ? __bfloat16_as_ushort(l1) : __bfloat16_as_ushort(h1);
        g_W1f[idx] = (uint32_t)u0 | ((uint32_t)u1 << 16);
    }
    // layer-2 B fragments: NT=2
    for (int idx = gt; idx < N_REL * 2 * 4 * 2 * 32 * 2; idx += nthreads) {
        int j    = idx & 1;
        int lane = (idx >> 1) & 31;
        int nt   = (idx >> 6) & 1;
        int ks   = (idx >> 7) & 3;
        int hl   = (idx >> 9) & 1;
        int rel  = idx >> 10;
        int n  = nt * 8 + (lane >> 2);
        int k0 = ks * 16 + (lane & 3) * 2 + j * 8;
        float w0 = 0.f, w1 = 0.f;
        #pragma unroll
        for (int b = 0; b < N_BASIS; b++) {
            float c = coeffs2[rel * N_BASIS + b];
            w0 += c * bases2[b * 1024 + k0 * 16 + n];
            w1 += c * bases2[b * 1024 + (k0 + 1) * 16 + n];
        }
        __nv_bfloat16 h0, l0, h1, l1;
        bf16_split(w0, h0, l0); bf16_split(w1, h1, l1);
        uint16_t u0 = hl ? __bfloat16_as_ushort(l0) : __bfloat16_as_ushort(h0);
        uint16_t u1 = hl ? __bfloat16_as_ushort(l1) : __bfloat16_as_ushort(h1);
        g_W2f[idx] = (uint32_t)u0 | ((uint32_t)u1 << 16);
    }
    for (int j = gt; j < N_NODES * 64; j += nthreads) {
        __nv_bfloat16 hi, lo; bf16_split(x[j], hi, lo);
        g_Xh[j] = hi; g_Xl[j] = lo;
    }
    for (int i = gt; i < N_REL * N_NODES; i += nthreads) g_cnt[i] = 0;
    for (int i = gt; i < ES; i += nthreads) { g_s[i] = 0; g_d[i] = 0; g_v[i] = 0.f; }
    if (gt < N_REL) { g_hist[gt] = 0; g_sortrel[gt] = 0; }
}

// ---------------- count + histogram ----------------
__global__ void k_counthist(const int* __restrict__ ei, const int* __restrict__ et)
{
    __shared__ int lh[N_REL];
    if (threadIdx.x < N_REL) lh[threadIdx.x] = 0;
    __syncthreads();
    int e = blockIdx.x * blockDim.x + threadIdx.x;
    if (e < N_EDGES) {
        int dst = __ldg(&ei[N_EDGES + e]);
        int t   = __ldg(&et[e]);
        atomicAdd(&g_cnt[t * N_NODES + dst], 1);
        atomicAdd(&lh[t], 1);
    }
    __syncthreads();
    if (threadIdx.x < N_REL && lh[threadIdx.x] > 0)
        atomicAdd(&g_hist[threadIdx.x], lh[threadIdx.x]);
}

// ---------------- counting-sort permute + inv ----------------
__global__ void k_permute(const int* __restrict__ ei, const int* __restrict__ et)
{
    __shared__ int spad[N_REL];
    if (threadIdx.x == 0) {
        int off = 0;
        #pragma unroll
        for (int r = 0; r < N_REL; r++) { spad[r] = off; off += ((g_hist[r] + 127) & ~127); }
    }
    __syncthreads();

    int e = blockIdx.x * blockDim.x + threadIdx.x;
    if (e >= N_EDGES) return;
    int src = __ldg(&ei[e]);
    int dst = __ldg(&ei[N_EDGES + e]);
    int t   = __ldg(&et[e]);
    int lane = threadIdx.x & 31;

    unsigned mask = __match_any_sync(__activemask(), t);
    int leader = __ffs(mask) - 1;
    int rank   = __popc(mask & ((1u << lane) - 1));
    int base = 0;
    if (lane == leader) base = atomicAdd(&g_sortrel[t], __popc(mask));
    base = __shfl_sync(__activemask(), base, leader);
    int pos = spad[t] + base + rank;

    int cnt = g_cnt[t * N_NODES + dst];
    g_s[pos] = src;
    g_d[pos] = dst;
    g_v[pos] = 1.0f / (float)(cnt > 0 ? cnt : 1);
}

// ---------------- split relu(h) into bf16 hi/lo ----------------
__global__ void k_splith()
{
    int j = blockIdx.x * blockDim.x + threadIdx.x;
    if (j >= N_NODES * 64) return;
    float v = fmaxf(g_h[j], 0.f);
    __nv_bfloat16 hi, lo; bf16_split(v, hi, lo);
    g_Hh[j] = hi; g_Hl[j] = lo;
}

// ---------------- HMMA fused edge GEMM: dest[dst] += inv * (X[src] @ W_rel) ----------------
// 128 edges/block, 4 warps; warp owns 2 m16 tiles. cp.async in 2 groups:
// {Ah, B} then {Al}; passes Ah*Wh+Ah*Wl after group0, Al*Wh after group1.
template<int NOUT, int MAXB>
__global__ __launch_bounds__(128, MAXB) void k_hmma(const __nv_bfloat16* __restrict__ Xh,
                                                    const __nv_bfloat16* __restrict__ Xl,
                                                    const uint32_t* __restrict__ Wf,
                                                    float* __restrict__ dest)
{
    constexpr int NT = NOUT / 8;                    // n-tiles (8 or 2)
    constexpr int WFREL = 2 * 4 * NT * 32 * 2;      // u32 per relation

    extern __shared__ __align__(128) char dsm[];
    // layout: Ah @0 (16KB), Al @16384 (16KB), B @32768 (WFREL*4)
    uint32_t* bfs = (uint32_t*)(dsm + 32768);

    __shared__ int   ssrc[128];
    __shared__ int   ds[128];
    __shared__ float vs[128];
    __shared__ int   spad[N_REL];

    const int tid = threadIdx.x, lane = tid & 31, wid = tid >> 5;
    const int b0 = blockIdx.x * 128;

    if (tid == 0) {
        int off = 0;
        #pragma unroll
        for (int r = 0; r < N_REL; r++) { spad[r] = off; off += ((g_hist[r] + 127) & ~127); }
    }
    ssrc[tid] = g_s[b0 + tid];
    ds[tid]   = g_d[b0 + tid];
    vs[tid]   = g_v[b0 + tid];
    __syncthreads();

    int rel = 0;
    #pragma unroll
    for (int i = 1; i < N_REL; i++)
        if (b0 >= spad[i]) rel = i;

    const uint32_t a_base = smem_u32(dsm);
    const uint32_t b_base = a_base + 32768;

    // group 0: Ah rows (per-warp) + B fragments (block-strided)
    #pragma unroll
    for (int i = 0; i < 8; i++) {
        int row = wid * 32 + i * 4 + (lane >> 3);
        int c   = (lane & 7) * 16;
        int src = ssrc[row];
        cp_async16(a_base + sw128((uint32_t)(row * 128 + c)),
                   (const char*)Xh + (size_t)src * 128 + c);
    }
    {
        const uint32_t* wsrc = Wf + (size_t)rel * WFREL;
        for (int i = tid * 4; i < WFREL; i += 128 * 4)
            cp_async16(b_base + i * 4, wsrc + i);
    }
    cp_commit();
    // group 1: Al rows (per-warp)
    #pragma unroll
    for (int i = 0; i < 8; i++) {
        int row = wid * 32 + i * 4 + (lane >> 3);
        int c   = (lane & 7) * 16;
        int src = ssrc[row];
        cp_async16(a_base + 16384 + sw128((uint32_t)(row * 128 + c)),
                   (const char*)Xl + (size_t)src * 128 + c);
    }
    cp_commit();

    cp_wait<1>();           // Ah + B ready
    __syncthreads();

    float acc[2][NT][4];
    #pragma unroll
    for (int mt = 0; mt < 2; mt++)
        #pragma unroll
        for (int nt = 0; nt < NT; nt++)
            #pragma unroll
            for (int j = 0; j < 4; j++) acc[mt][nt][j] = 0.f;

    const int lrow = lane & 15;
    const int lkh  = lane >> 4;

    // passes 1+2: Ah*Wh and Ah*Wl
    #pragma unroll
    for (int ks = 0; ks < 4; ks++) {
        uint32_t bh[NT][2], bl[NT][2];
        #pragma unroll
        for (int nt = 0; nt < NT; nt++) {
            const uint32_t* ph = bfs + (((0 * 4 + ks) * NT + nt) * 32 + lane) * 2;
            const uint32_t* pl = bfs + (((1 * 4 + ks) * NT + nt) * 32 + lane) * 2;
            bh[nt][0] = ph[0]; bh[nt][1] = ph[1];
            bl[nt][0] = pl[0]; bl[nt][1] = pl[1];
        }
        #pragma unroll
        for (int mt = 0; mt < 2; mt++) {
            int row = wid * 32 + mt * 16 + lrow;
            int c   = ks * 2 + lkh;
            uint32_t off = (uint32_t)(row * 128) + (uint32_t)((c ^ (row & 7)) << 4);
            uint32_t ah0, ah1, ah2, ah3;
            ldm_x4(ah0, ah1, ah2, ah3, a_base + off);
            #pragma unroll
            for (int nt = 0; nt < NT; nt++) {
                mma_bf16(acc[mt][nt][0], acc[mt][nt][1], acc[mt][nt][2], acc[mt][nt][3],
                         ah0, ah1, ah2, ah3, bh[nt][0], bh[nt][1]);
                mma_bf16(acc[mt][nt][0], acc[mt][nt][1], acc[mt][nt][2], acc[mt][nt][3],
                         ah0, ah1, ah2, ah3, bl[nt][0], bl[nt][1]);
            }
        }
    }

    cp_wait<0>();           // Al ready (staged by this warp only)
    __syncwarp();

    // pass 3: Al*Wh
    #pragma unroll
    for (int ks = 0; ks < 4; ks++) {
        uint32_t bh[NT][2];
        #pragma unroll
        for (int nt = 0; nt < NT; nt++) {
            const uint32_t* ph = bfs + (((0 * 4 + ks) * NT + nt) * 32 + lane) * 2;
            bh[nt][0] = ph[0]; bh[nt][1] = ph[1];
        }
        #pragma unroll
        for (int mt = 0; mt < 2; mt++) {
            int row = wid * 32 + mt * 16 + lrow;
            int c   = ks * 2 + lkh;
            uint32_t off = (uint32_t)(row * 128) + (uint32_t)((c ^ (row & 7)) << 4);
            uint32_t al0, al1, al2, al3;
            ldm_x4(al0, al1, al2, al3, a_base + 16384 + off);
            #pragma unroll
            for (int nt = 0; nt < NT; nt++) {
                mma_bf16(acc[mt][nt][0], acc[mt][nt][1], acc[mt][nt][2], acc[mt][nt][3],
                         al0, al1, al2, al3, bh[nt][0], bh[nt][1]);
            }
        }
    }

    // epilogue: pair-exchange via shfl.xor(1) -> one red.v4 per (mt, nt)
    const int q    = lane & 3;
    const int crow = lane >> 2;
    const bool odd = (lane & 1);
    #pragma unroll
    for (int mt = 0; mt < 2; mt++) {
        int rowE = wid * 32 + mt * 16 + crow;
        int row  = odd ? rowE + 8 : rowE;
        float inv = vs[row];
        float* rp = dest + (size_t)ds[row] * NOUT;
        int colbase = odd ? 2 * (q - 1) : 2 * q;
        #pragma unroll
        for (int nt = 0; nt < NT; nt++) {
            float s0 = odd ? acc[mt][nt][0] : acc[mt][nt][2];
            float s1 = odd ? acc[mt][nt][1] : acc[mt][nt][3];
            unsigned long long pk;
            asm("mov.b64 %0, {%1, %2};" : "=l"(pk) : "f"(s0), "f"(s1));
            unsigned long long rk = __shfl_xor_sync(0xFFFFFFFFu, pk, 1);
            float r0, r1;
            asm("mov.b64 {%0, %1}, %2;" : "=f"(r0), "=f"(r1) : "l"(rk));
            float v0, v1, v2, v3;
            if (odd) { v0 = r0; v1 = r1; v2 = acc[mt][nt][2]; v3 = acc[mt][nt][3]; }
            else     { v0 = acc[mt][nt][0]; v1 = acc[mt][nt][1]; v2 = r0; v3 = r1; }
            red_v4(rp + nt * 8 + colbase, v0 * inv, v1 * inv, v2 * inv, v3 * inv);
        }
    }
}

// ---------------- dense self-term GEMM (exact f32): OUT (+)= act(X) @ W ----------------
template<int NOUT, bool RELU, bool ATOMIC>
__global__ __launch_bounds__(128) void k_dense(const float* __restrict__ X,
                                               const float* __restrict__ W,
                                               float* __restrict__ OUT)
{
    constexpr int TO  = NOUT / 4;
    constexpr int NW2 = TO / 2;

    __shared__ float xs[64][128];
    __shared__ float ws[64 * NOUT];

    const int tid  = threadIdx.x;
    const int lane = tid & 31;
    const int og   = tid >> 5;
    const int b0   = blockIdx.x * 128;

    #pragma unroll
    for (int i = 0; i < 16; i++) {
        int row = og * 32 + i * 2 + (lane >> 4);
        int g   = lane & 15;
        int node = b0 + row;
        float4 v = make_float4(0.f, 0.f, 0.f, 0.f);
        if (node < N_NODES) v = __ldg((const float4*)(X + (size_t)node * 64 + g * 4));
        if (RELU) {
            v.x = fmaxf(v.x, 0.f); v.y = fmaxf(v.y, 0.f);
            v.z = fmaxf(v.z, 0.f); v.w = fmaxf(v.w, 0.f);
        }
        int mp = row ^ ((g & 7) << 2);
        xs[4 * g + 0][mp] = v.x;
        xs[4 * g + 1][mp] = v.y;
        xs[4 * g + 2][mp] = v.z;
        xs[4 * g + 3][mp] = v.w;
    }
    for (int i = tid * 4; i < 64 * NOUT; i += 128 * 4)
        *(float4*)(ws + i) = *(const float4*)(W + i);
    __syncthreads();

    const int o0 = og * TO;
    const int m0 = lane * 4;

    unsigned long long acc[4][NW2];
    #pragma unroll
    for (int i = 0; i < 4; i++)
        #pragma unroll
        for (int j = 0; j < NW2; j++) acc[i][j] = 0ull;

    #pragma unroll 8
    for (int k = 0; k < 64; k++) {
        float4 xv = *(const float4*)&xs[k][m0 ^ (k & 28)];
        unsigned long long x2[4];
        asm("mov.b64 %0, {%1, %1};" : "=l"(x2[0]) : "f"(xv.x));
        asm("mov.b64 %0, {%1, %1};" : "=l"(x2[1]) : "f"(xv.y));
        asm("mov.b64 %0, {%1, %1};" : "=l"(x2[2]) : "f"(xv.z));
        asm("mov.b64 %0, {%1, %1};" : "=l"(x2[3]) : "f"(xv.w));
        unsigned long long w2[NW2];
        #pragma unroll
        for (int q = 0; q < TO / 4; q++) {
            float4 wa = *(const float4*)(ws + k * NOUT + o0 + q * 4);
            asm("mov.b64 %0, {%1, %2};" : "=l"(w2[q * 2 + 0]) : "f"(wa.x), "f"(wa.y));
            asm("mov.b64 %0, {%1, %2};" : "=l"(w2[q * 2 + 1]) : "f"(wa.z), "f"(wa.w));
        }
        #pragma unroll
        for (int j = 0; j < NW2; j++)
            #pragma unroll
            for (int i = 0; i < 4; i++)
                asm("fma.rn.f32x2 %0, %1, %2, %0;" : "+l"(acc[i][j]) : "l"(x2[i]), "l"(w2[j]));
    }

    #pragma unroll
    for (int i = 0; i < 4; i++) {
        int node = b0 + m0 + i;
        if (node < N_NODES) {
            float* op = OUT + (size_t)node * NOUT + o0;
            #pragma unroll
            for (int j = 0; j < NW2; j += 2) {
                float2 a = *(float2*)&acc[i][j];
                float2 b = *(float2*)&acc[i][j + 1];
                if (ATOMIC) red_v4(op + 2 * j, a.x, a.y, b.x, b.y);
                else *(float4*)(op + 2 * j) = make_float4(a.x, a.y, b.x, b.y);
            }
        }
    }
}

// ---------------- launch ----------------
extern "C" void kernel_launch(void* const* d_in, const int* in_sizes, int n_in,
                              void* d_out, int out_size)
{
    const float* x       = (const float*)d_in[0];
    const float* bases1  = (const float*)d_in[1];
    const float* coeffs1 = (const float*)d_in[2];
    const float* self1   = (const float*)d_in[3];
    const float* bases2  = (const float*)d_in[4];
    const float* coeffs2 = (const float*)d_in[5];
    const float* self2   = (const float*)d_in[6];
    const int* ei        = (const int*)d_in[7];
    const int* et        = (const int*)d_in[8];
    float* out = (float*)d_out;

    const int NODE_TILES = (N_NODES + 127) / 128;   // 391
    const int DSM1 = 32768 + 2 * 4 * 8 * 32 * 2 * 4;   // 49152
    const int DSM2 = 32768 + 2 * 4 * 2 * 32 * 2 * 4;   // 36864

    float* hp;  cudaGetSymbolAddress((void**)&hp,  g_h);
    uint32_t *w1f, *w2f;
    cudaGetSymbolAddress((void**)&w1f, g_W1f);
    cudaGetSymbolAddress((void**)&w2f, g_W2f);
    __nv_bfloat16 *xh, *xl, *hh, *hl;
    cudaGetSymbolAddress((void**)&xh, g_Xh);
    cudaGetSymbolAddress((void**)&xl, g_Xl);
    cudaGetSymbolAddress((void**)&hh, g_Hh);
    cudaGetSymbolAddress((void**)&hl, g_Hl);

    cudaFuncSetAttribute((const void*)k_hmma<D_HID, 4>,
                         cudaFuncAttributeMaxDynamicSharedMemorySize, DSM1);
    cudaFuncSetAttribute((const void*)k_hmma<N_CLASS, 5>,
                         cudaFuncAttributeMaxDynamicSharedMemorySize, DSM2);

    // #1 W fragments (split, mma lane layout) + X split + zero state
    k_init<<<1024, 256>>>(bases1, coeffs1, bases2, coeffs2, x);
    // #2 counts + histogram
    k_counthist<<<(N_EDGES + 255) / 256, 256>>>(ei, et);
    // #3 counting-sort by relation
    k_permute<<<(N_EDGES + 255) / 256, 256>>>(ei, et);
    // #4 h = x @ self1 (plain store, covers h) -- before edge atomics
    k_dense<D_HID, false, false><<<NODE_TILES, 128>>>(x, self1, hp);
    // #5 layer-1 fused HMMA edge GEMM -> atomic into h
    k_hmma<D_HID, 4><<<NBLK_E, 128, DSM1>>>(xh, xl, w1f, hp);
    // #6 relu + bf16-split h
    k_splith<<<(N_NODES * 64 + 255) / 256, 256>>>();
    // #7 out = relu(h) @ self2 (plain store covers out)
    k_dense<N_CLASS, true, false><<<NODE_TILES, 128>>>(hp, self2, out);
    // #8 layer-2 fused HMMA edge GEMM -> atomic into out
    k_hmma<N_CLASS, 5><<<NBLK_E, 128, DSM2>>>(hh, hl, w2f, out);
}

// round 17
// speedup vs baseline: 1.1684x; 1.0695x over previous
#include <cuda_runtime.h>
#include <cuda_bf16.h>
#include <cstdint>

#define N_NODES 50000
#define N_REL   16
#define N_BASIS 8
#define D_IN    64
#define D_HID   64
#define N_CLASS 16
#define N_EDGES 800000

#define ES      802176              // 6267 * 128 (16 bins padded to 128)
#define NBLK_E  6267
#define NBLK_S  391                 // self-term blocks: ceil(50000/128)
#define NBLK_T  (NBLK_E + NBLK_S)

// ---------------- device scratch ----------------
// B fragments for mma.sync m16n8k16 row.col, PTX-lane layout, 17 relations
// (rel 16 = self weights): idx = ((((rel*2 + hl)*4 + ks)*NT + nt)*32 + lane)*2 + j
__device__ __align__(16) uint32_t g_W1f[(N_REL + 1) * 2 * 4 * 8 * 32 * 2];   // 136 KB
__device__ __align__(16) uint32_t g_W2f[(N_REL + 1) * 2 * 4 * 2 * 32 * 2];   // 34 KB
__device__ __align__(16) __nv_bfloat16 g_Xh[N_NODES * 64];
__device__ __align__(16) __nv_bfloat16 g_Xl[N_NODES * 64];
__device__ __align__(16) __nv_bfloat16 g_Hh[N_NODES * 64];
__device__ __align__(16) __nv_bfloat16 g_Hl[N_NODES * 64];
__device__ __align__(16) float g_h [N_NODES * D_HID];
__device__ __align__(16) int   g_cnt[N_REL * N_NODES];
__device__ int   g_hist[N_REL];
__device__ int   g_sortrel[N_REL];
__device__ __align__(16) int   g_s[ES];
__device__ __align__(16) int   g_d[ES];
__device__ __align__(16) float g_v[ES];

// ---------------- helpers ----------------
__device__ __forceinline__ uint32_t sw128(uint32_t o) { return o ^ ((o >> 3) & 0x70); }
__device__ __forceinline__ uint32_t smem_u32(const void* p) {
    uint32_t a;
    asm("{ .reg .u64 t; cvta.to.shared.u64 t, %1; cvt.u32.u64 %0, t; }" : "=r"(a) : "l"(p));
    return a;
}
__device__ __forceinline__ void cp_async16(uint32_t dst, const void* src) {
    asm volatile("cp.async.cg.shared.global [%0], [%1], 16;" :: "r"(dst), "l"(src) : "memory");
}
__device__ __forceinline__ void cp_commit() {
    asm volatile("cp.async.commit_group;" ::: "memory");
}
template<int N>
__device__ __forceinline__ void cp_wait() {
    asm volatile("cp.async.wait_group %0;" :: "n"(N) : "memory");
}
__device__ __forceinline__ void red_v4(float* p, float a, float b, float c, float d) {
    asm volatile("red.global.add.v4.f32 [%0], {%1, %2, %3, %4};"
                 :: "l"(p), "f"(a), "f"(b), "f"(c), "f"(d) : "memory");
}
__device__ __forceinline__ void bf16_split(float v, __nv_bfloat16& hi, __nv_bfloat16& lo) {
    hi = __float2bfloat16(v);
    lo = __float2bfloat16(v - __bfloat162float(hi));
}
__device__ __forceinline__ void ldm_x4(uint32_t& a0, uint32_t& a1, uint32_t& a2, uint32_t& a3,
                                       uint32_t addr) {
    asm volatile("ldmatrix.sync.aligned.m8n8.x4.shared.b16 {%0,%1,%2,%3}, [%4];"
                 : "=r"(a0), "=r"(a1), "=r"(a2), "=r"(a3) : "r"(addr));
}
__device__ __forceinline__ void mma_bf16(float& c0, float& c1, float& c2, float& c3,
                                         uint32_t a0, uint32_t a1, uint32_t a2, uint32_t a3,
                                         uint32_t b0, uint32_t b1) {
    asm volatile("mma.sync.aligned.m16n8k16.row.col.f32.bf16.bf16.f32 "
                 "{%0,%1,%2,%3}, {%4,%5,%6,%7}, {%8,%9}, {%0,%1,%2,%3};"
                 : "+f"(c0), "+f"(c1), "+f"(c2), "+f"(c3)
                 : "r"(a0), "r"(a1), "r"(a2), "r"(a3), "r"(b0), "r"(b1));
}

// ---------------- init: W frags (17 rels), X split, zero state + h + out ----------------
__global__ void k_init(const float* __restrict__ bases1, const float* __restrict__ coeffs1,
                       const float* __restrict__ self1,
                       const float* __restrict__ bases2, const float* __restrict__ coeffs2,
                       const float* __restrict__ self2,
                       const float* __restrict__ x, float* __restrict__ out)
{
    int nthreads = gridDim.x * blockDim.x;
    int gt = blockIdx.x * blockDim.x + threadIdx.x;

    // layer-1 B fragments: NT=8, 17 relations (rel 16 = self1)
    for (int idx = gt; idx < (N_REL + 1) * 2 * 4 * 8 * 32 * 2; idx += nthreads) {
        int j    = idx & 1;
        int lane = (idx >> 1) & 31;
        int nt   = (idx >> 6) & 7;
        int ks   = (idx >> 9) & 3;
        int hl   = (idx >> 11) & 1;
        int rel  = idx >> 12;
        int n  = nt * 8 + (lane >> 2);
        int k0 = ks * 16 + (lane & 3) * 2 + j * 8;
        float w0, w1;
        if (rel < N_REL) {
            w0 = 0.f; w1 = 0.f;
            #pragma unroll
            for (int b = 0; b < N_BASIS; b++) {
                float c = coeffs1[rel * N_BASIS + b];
                w0 += c * bases1[b * 4096 + k0 * 64 + n];
                w1 += c * bases1[b * 4096 + (k0 + 1) * 64 + n];
            }
        } else {
            w0 = self1[k0 * 64 + n];
            w1 = self1[(k0 + 1) * 64 + n];
        }
        __nv_bfloat16 h0, l0, h1, l1;
        bf16_split(w0, h0, l0); bf16_split(w1, h1, l1);
        uint16_t u0 = hl ? __bfloat16_as_ushort(l0) : __bfloat16_as_ushort(h0);
        uint16_t u1 = hl ? __bfloat16_as_ushort(l1) : __bfloat16_as_ushort(h1);
        g_W1f[idx] = (uint32_t)u0 | ((uint32_t)u1 << 16);
    }
    // layer-2 B fragments: NT=2, 17 relations (rel 16 = self2)
    for (int idx = gt; idx < (N_REL + 1) * 2 * 4 * 2 * 32 * 2; idx += nthreads) {
        int j    = idx & 1;
        int lane = (idx >> 1) & 31;
        int nt   = (idx >> 6) & 1;
        int ks   = (idx >> 7) & 3;
        int hl   = (idx >> 9) & 1;
        int rel  = idx >> 10;
        int n  = nt * 8 + (lane >> 2);
        int k0 = ks * 16 + (lane & 3) * 2 + j * 8;
        float w0, w1;
        if (rel < N_REL) {
            w0 = 0.f; w1 = 0.f;
            #pragma unroll
            for (int b = 0; b < N_BASIS; b++) {
                float c = coeffs2[rel * N_BASIS + b];
                w0 += c * bases2[b * 1024 + k0 * 16 + n];
                w1 += c * bases2[b * 1024 + (k0 + 1) * 16 + n];
            }
        } else {
            w0 = self2[k0 * 16 + n];
            w1 = self2[(k0 + 1) * 16 + n];
        }
        __nv_bfloat16 h0, l0, h1, l1;
        bf16_split(w0, h0, l0); bf16_split(w1, h1, l1);
        uint16_t u0 = hl ? __bfloat16_as_ushort(l0) : __bfloat16_as_ushort(h0);
        uint16_t u1 = hl ? __bfloat16_as_ushort(l1) : __bfloat16_as_ushort(h1);
        g_W2f[idx] = (uint32_t)u0 | ((uint32_t)u1 << 16);
    }
    for (int j = gt; j < N_NODES * 64; j += nthreads) {
        __nv_bfloat16 hi, lo; bf16_split(x[j], hi, lo);
        g_Xh[j] = hi; g_Xl[j] = lo;
    }
    for (int i = gt; i < N_REL * N_NODES; i += nthreads) g_cnt[i] = 0;
    for (int i = gt; i < ES; i += nthreads) { g_s[i] = 0; g_d[i] = 0; g_v[i] = 0.f; }
    for (int i = gt; i < N_NODES * D_HID / 4; i += nthreads)
        ((float4*)g_h)[i] = make_float4(0.f, 0.f, 0.f, 0.f);
    for (int i = gt; i < N_NODES * N_CLASS / 4; i += nthreads)
        ((float4*)out)[i] = make_float4(0.f, 0.f, 0.f, 0.f);
    if (gt < N_REL) { g_hist[gt] = 0; g_sortrel[gt] = 0; }
}

// ---------------- count + histogram ----------------
__global__ void k_counthist(const int* __restrict__ ei, const int* __restrict__ et)
{
    __shared__ int lh[N_REL];
    if (threadIdx.x < N_REL) lh[threadIdx.x] = 0;
    __syncthreads();
    int e = blockIdx.x * blockDim.x + threadIdx.x;
    if (e < N_EDGES) {
        int dst = __ldg(&ei[N_EDGES + e]);
        int t   = __ldg(&et[e]);
        atomicAdd(&g_cnt[t * N_NODES + dst], 1);
        atomicAdd(&lh[t], 1);
    }
    __syncthreads();
    if (threadIdx.x < N_REL && lh[threadIdx.x] > 0)
        atomicAdd(&g_hist[threadIdx.x], lh[threadIdx.x]);
}

// ---------------- counting-sort permute + inv ----------------
__global__ void k_permute(const int* __restrict__ ei, const int* __restrict__ et)
{
    __shared__ int spad[N_REL];
    if (threadIdx.x == 0) {
        int off = 0;
        #pragma unroll
        for (int r = 0; r < N_REL; r++) { spad[r] = off; off += ((g_hist[r] + 127) & ~127); }
    }
    __syncthreads();

    int e = blockIdx.x * blockDim.x + threadIdx.x;
    if (e >= N_EDGES) return;
    int src = __ldg(&ei[e]);
    int dst = __ldg(&ei[N_EDGES + e]);
    int t   = __ldg(&et[e]);
    int lane = threadIdx.x & 31;

    unsigned mask = __match_any_sync(__activemask(), t);
    int leader = __ffs(mask) - 1;
    int rank   = __popc(mask & ((1u << lane) - 1));
    int base = 0;
    if (lane == leader) base = atomicAdd(&g_sortrel[t], __popc(mask));
    base = __shfl_sync(__activemask(), base, leader);
    int pos = spad[t] + base + rank;

    int cnt = g_cnt[t * N_NODES + dst];
    g_s[pos] = src;
    g_d[pos] = dst;
    g_v[pos] = 1.0f / (float)(cnt > 0 ? cnt : 1);
}

// ---------------- split relu(h) into bf16 hi/lo ----------------
__global__ void k_splith()
{
    int j = blockIdx.x * blockDim.x + threadIdx.x;
    if (j >= N_NODES * 64) return;
    float v = fmaxf(g_h[j], 0.f);
    __nv_bfloat16 hi, lo; bf16_split(v, hi, lo);
    g_Hh[j] = hi; g_Hl[j] = lo;
}

// ---------------- HMMA fused edge+self GEMM: dest[dst] += inv * (X[src] @ W_rel) --------
// Edge blocks (< NBLK_E): 128 relation-sorted edges, rel from bin offsets.
// Self blocks (>= NBLK_E): 128 nodes, src=dst=node, inv=1, rel=16 (self weights).
// 4 warps; warp owns 2 m16 tiles. cp.async in 2 groups: {Ah, B} then {Al}.
template<int NOUT, int MAXB>
__global__ __launch_bounds__(128, MAXB) void k_hmma(const __nv_bfloat16* __restrict__ Xh,
                                                    const __nv_bfloat16* __restrict__ Xl,
                                                    const uint32_t* __restrict__ Wf,
                                                    float* __restrict__ dest)
{
    constexpr int NT = NOUT / 8;                    // n-tiles (8 or 2)
    constexpr int WFREL = 2 * 4 * NT * 32 * 2;      // u32 per relation

    extern __shared__ __align__(128) char dsm[];
    // layout: Ah @0 (16KB), Al @16384 (16KB), B @32768 (WFREL*4)
    uint32_t* bfs = (uint32_t*)(dsm + 32768);

    __shared__ int   ssrc[128];
    __shared__ int   ds[128];
    __shared__ float vs[128];
    __shared__ int   spad[N_REL];

    const int tid = threadIdx.x, lane = tid & 31, wid = tid >> 5;
    const bool self_blk = (blockIdx.x >= NBLK_E);
    const int b0 = blockIdx.x * 128;

    int rel;
    if (self_blk) {
        int node = (blockIdx.x - NBLK_E) * 128 + tid;
        bool ok = node < N_NODES;
        ssrc[tid] = ok ? node : 0;
        ds[tid]   = ok ? node : 0;
        vs[tid]   = ok ? 1.f : 0.f;
        rel = N_REL;
        __syncthreads();
    } else {
        if (tid == 0) {
            int off = 0;
            #pragma unroll
            for (int r = 0; r < N_REL; r++) { spad[r] = off; off += ((g_hist[r] + 127) & ~127); }
        }
        ssrc[tid] = g_s[b0 + tid];
        ds[tid]   = g_d[b0 + tid];
        vs[tid]   = g_v[b0 + tid];
        __syncthreads();
        rel = 0;
        #pragma unroll
        for (int i = 1; i < N_REL; i++)
            if (b0 >= spad[i]) rel = i;
    }

    const uint32_t a_base = smem_u32(dsm);
    const uint32_t b_base = a_base + 32768;

    // group 0: Ah rows (per-warp) + B fragments (block-strided)
    #pragma unroll
    for (int i = 0; i < 8; i++) {
        int row = wid * 32 + i * 4 + (lane >> 3);
        int c   = (lane & 7) * 16;
        int src = ssrc[row];
        cp_async16(a_base + sw128((uint32_t)(row * 128 + c)),
                   (const char*)Xh + (size_t)src * 128 + c);
    }
    {
        const uint32_t* wsrc = Wf + (size_t)rel * WFREL;
        for (int i = tid * 4; i < WFREL; i += 128 * 4)
            cp_async16(b_base + i * 4, wsrc + i);
    }
    cp_commit();
    // group 1: Al rows (per-warp)
    #pragma unroll
    for (int i = 0; i < 8; i++) {
        int row = wid * 32 + i * 4 + (lane >> 3);
        int c   = (lane & 7) * 16;
        int src = ssrc[row];
        cp_async16(a_base + 16384 + sw128((uint32_t)(row * 128 + c)),
                   (const char*)Xl + (size_t)src * 128 + c);
    }
    cp_commit();

    cp_wait<1>();           // Ah + B ready
    __syncthreads();

    float acc[2][NT][4];
    #pragma unroll
    for (int mt = 0; mt < 2; mt++)
        #pragma unroll
        for (int nt = 0; nt < NT; nt++)
            #pragma unroll
            for (int j = 0; j < 4; j++) acc[mt][nt][j] = 0.f;

    const int lrow = lane & 15;
    const int lkh  = lane >> 4;

    // passes 1+2: Ah*Wh and Ah*Wl
    #pragma unroll
    for (int ks = 0; ks < 4; ks++) {
        uint32_t bh[NT][2], bl[NT][2];
        #pragma unroll
        for (int nt = 0; nt < NT; nt++) {
            const uint32_t* ph = bfs + (((0 * 4 + ks) * NT + nt) * 32 + lane) * 2;
            const uint32_t* pl = bfs + (((1 * 4 + ks) * NT + nt) * 32 + lane) * 2;
            bh[nt][0] = ph[0]; bh[nt][1] = ph[1];
            bl[nt][0] = pl[0]; bl[nt][1] = pl[1];
        }
        #pragma unroll
        for (int mt = 0; mt < 2; mt++) {
            int row = wid * 32 + mt * 16 + lrow;
            int c   = ks * 2 + lkh;
            uint32_t off = (uint32_t)(row * 128) + (uint32_t)((c ^ (row & 7)) << 4);
            uint32_t ah0, ah1, ah2, ah3;
            ldm_x4(ah0, ah1, ah2, ah3, a_base + off);
            #pragma unroll
            for (int nt = 0; nt < NT; nt++) {
                mma_bf16(acc[mt][nt][0], acc[mt][nt][1], acc[mt][nt][2], acc[mt][nt][3],
                         ah0, ah1, ah2, ah3, bh[nt][0], bh[nt][1]);
                mma_bf16(acc[mt][nt][0], acc[mt][nt][1], acc[mt][nt][2], acc[mt][nt][3],
                         ah0, ah1, ah2, ah3, bl[nt][0], bl[nt][1]);
            }
        }
    }

    cp_wait<0>();           // Al ready (staged by this warp only)
    __syncwarp();

    // pass 3: Al*Wh
    #pragma unroll
    for (int ks = 0; ks < 4; ks++) {
        uint32_t bh[NT][2];
        #pragma unroll
        for (int nt = 0; nt < NT; nt++) {
            const uint32_t* ph = bfs + (((0 * 4 + ks) * NT + nt) * 32 + lane) * 2;
            bh[nt][0] = ph[0]; bh[nt][1] = ph[1];
        }
        #pragma unroll
        for (int mt = 0; mt < 2; mt++) {
            int row = wid * 32 + mt * 16 + lrow;
            int c   = ks * 2 + lkh;
            uint32_t off = (uint32_t)(row * 128) + (uint32_t)((c ^ (row & 7)) << 4);
            uint32_t al0, al1, al2, al3;
            ldm_x4(al0, al1, al2, al3, a_base + 16384 + off);
            #pragma unroll
            for (int nt = 0; nt < NT; nt++) {
                mma_bf16(acc[mt][nt][0], acc[mt][nt][1], acc[mt][nt][2], acc[mt][nt][3],
                         al0, al1, al2, al3, bh[nt][0], bh[nt][1]);
            }
        }
    }

    // epilogue: pair-exchange via shfl.xor(1) -> one red.v4 per (mt, nt)
    const int q    = lane & 3;
    const int crow = lane >> 2;
    const bool odd = (lane & 1);
    #pragma unroll
    for (int mt = 0; mt < 2; mt++) {
        int rowE = wid * 32 + mt * 16 + crow;
        int row  = odd ? rowE + 8 : rowE;
        float inv = vs[row];
        float* rp = dest + (size_t)ds[row] * NOUT;
        int colbase = odd ? 2 * (q - 1) : 2 * q;
        #pragma unroll
        for (int nt = 0; nt < NT; nt++) {
            float s0 = odd ? acc[mt][nt][0] : acc[mt][nt][2];
            float s1 = odd ? acc[mt][nt][1] : acc[mt][nt][3];
            unsigned long long pk;
            asm("mov.b64 %0, {%1, %2};" : "=l"(pk) : "f"(s0), "f"(s1));
            unsigned long long rk = __shfl_xor_sync(0xFFFFFFFFu, pk, 1);
            float r0, r1;
            asm("mov.b64 {%0, %1}, %2;" : "=f"(r0), "=f"(r1) : "l"(rk));
            float v0, v1, v2, v3;
            if (odd) { v0 = r0; v1 = r1; v2 = acc[mt][nt][2]; v3 = acc[mt][nt][3]; }
            else     { v0 = acc[mt][nt][0]; v1 = acc[mt][nt][1]; v2 = r0; v3 = r1; }
            red_v4(rp + nt * 8 + colbase, v0 * inv, v1 * inv, v2 * inv, v3 * inv);
        }
    }
}

// ---------------- launch ----------------
extern "C" void kernel_launch(void* const* d_in, const int* in_sizes, int n_in,
                              void* d_out, int out_size)
{
    const float* x       = (const float*)d_in[0];
    const float* bases1  = (const float*)d_in[1];
    const float* coeffs1 = (const float*)d_in[2];
    const float* self1   = (const float*)d_in[3];
    const float* bases2  = (const float*)d_in[4];
    const float* coeffs2 = (const float*)d_in[5];
    const float* self2   = (const float*)d_in[6];
    const int* ei        = (const int*)d_in[7];
    const int* et        = (const int*)d_in[8];
    float* out = (float*)d_out;

    const int DSM1 = 32768 + 2 * 4 * 8 * 32 * 2 * 4;   // 49152
    const int DSM2 = 32768 + 2 * 4 * 2 * 32 * 2 * 4;   // 36864

    float* hp;  cudaGetSymbolAddress((void**)&hp,  g_h);
    uint32_t *w1f, *w2f;
    cudaGetSymbolAddress((void**)&w1f, g_W1f);
    cudaGetSymbolAddress((void**)&w2f, g_W2f);
    __nv_bfloat16 *xh, *xl, *hh, *hl;
    cudaGetSymbolAddress((void**)&xh, g_Xh);
    cudaGetSymbolAddress((void**)&xl, g_Xl);
    cudaGetSymbolAddress((void**)&hh, g_Hh);
    cudaGetSymbolAddress((void**)&hl, g_Hl);

    cudaFuncSetAttribute((const void*)k_hmma<D_HID, 4>,
                         cudaFuncAttributeMaxDynamicSharedMemorySize, DSM1);
    cudaFuncSetAttribute((const void*)k_hmma<N_CLASS, 5>,
                         cudaFuncAttributeMaxDynamicSharedMemorySize, DSM2);

    // #1 W fragments (17 rels incl. self) + X split + zero cnt/sort/h/out
    k_init<<<1024, 256>>>(bases1, coeffs1, self1, bases2, coeffs2, self2, x, out);
    // #2 counts + histogram
    k_counthist<<<(N_EDGES + 255) / 256, 256>>>(ei, et);
    // #3 counting-sort by relation
    k_permute<<<(N_EDGES + 255) / 256, 256>>>(ei, et);
    // #4 layer-1 fused HMMA (edges + self blocks) -> atomic into h (zeroed in init)
    k_hmma<D_HID, 4><<<NBLK_T, 128, DSM1>>>(xh, xl, w1f, hp);
    // #5 relu + bf16-split h
    k_splith<<<(N_NODES * 64 + 255) / 256, 256>>>();
    // #6 layer-2 fused HMMA (edges + self blocks) -> atomic into out (zeroed in init)
    k_hmma<N_CLASS, 5><<<NBLK_T, 128, DSM2>>>(hh, hl, w2f, out);
}